// round 2
// baseline (speedup 1.0000x reference)
#include <cuda_runtime.h>
#include <math.h>

#define Bb 16
#define Tt 2048
#define Ii 512
#define Hh 512
#define RR 2048   // 4*H, permuted row order r = 4*j + g

// ---------------- persistent device scratch (no runtime allocation) ----------
__device__ float d_WiP[RR * Ii];                       // 4 MB  permuted Wi
__device__ float d_WhP[RR * Hh];                       // 4 MB  permuted Wh
__device__ float d_bsum[RR];                           // bi+bh, permuted
__device__ float d_XG[(size_t)Tt * RR * Bb];           // 268 MB, [t][r][b]
__device__ float d_HBUF[2][Hh * Bb];                   // double-buffered h, [k][b]
__device__ unsigned d_bar_count;
__device__ volatile unsigned d_bar_flag;

// ---------------- phase 0a: permute weights, fuse biases ---------------------
__global__ void permute_kernel(const float* __restrict__ Wi,
                               const float* __restrict__ Wh,
                               const float* __restrict__ bi,
                               const float* __restrict__ bh) {
    int rnew = blockIdx.x;            // 0..2047
    int j = rnew >> 2, g = rnew & 3;
    int rold = g * Hh + j;
    const float4* wi4 = (const float4*)(Wi + (size_t)rold * Ii);
    const float4* wh4 = (const float4*)(Wh + (size_t)rold * Hh);
    float4* wiP4 = (float4*)(d_WiP + (size_t)rnew * Ii);
    float4* whP4 = (float4*)(d_WhP + (size_t)rnew * Hh);
    for (int k = threadIdx.x; k < Ii / 4; k += blockDim.x) wiP4[k] = wi4[k];
    for (int k = threadIdx.x; k < Hh / 4; k += blockDim.x) whP4[k] = wh4[k];
    if (threadIdx.x == 0) d_bsum[rnew] = bi[rold] + bh[rold];
}

// ---------------- phase 0b: init h buffer + barrier state --------------------
__global__ void init_kernel(const float* __restrict__ h0) {
    int idx = blockIdx.x * blockDim.x + threadIdx.x;   // 0..8191
    if (idx < Hh * Bb) {
        int j = idx >> 4, b = idx & 15;
        d_HBUF[0][idx] = h0[b * Hh + j];               // h_s layout [k][b]
    }
    if (idx == 0) { d_bar_count = 0u; d_bar_flag = 0u; }
}

// ---------------- phase 1: xg[t][r][b] = WiP @ x^T + bsum --------------------
// GEMM: M=2048 (r), N=32768 (n=(t,b)), K=512.  X[i][n] = x[b][t][i] (contig in i).
#define BM 128
#define BN 128
#define BK 16
#define LDA 132

__global__ __launch_bounds__(256, 2) void xgemm_kernel(const float* __restrict__ x) {
    __shared__ float As[BK * LDA];
    __shared__ float Bs[BK * LDA];
    const int tid = threadIdx.x;
    const int m0 = blockIdx.y * BM;
    const int n0 = blockIdx.x * BN;
    const int tx = tid & 15, ty = tid >> 4;

    float acc[8][8];
#pragma unroll
    for (int i = 0; i < 8; i++)
#pragma unroll
        for (int j = 0; j < 8; j++) acc[i][j] = 0.f;

    for (int k0 = 0; k0 < Ii; k0 += BK) {
        // A tile: 128 rows x 16 k  (512 float4 slots)
#pragma unroll
        for (int q = 0; q < 2; q++) {
            int slot = tid + q * 256;
            int row = slot >> 2;
            int kq4 = slot & 3;
            float4 v = *(const float4*)&d_WiP[(size_t)(m0 + row) * Ii + k0 + kq4 * 4];
            As[(kq4 * 4 + 0) * LDA + row] = v.x;
            As[(kq4 * 4 + 1) * LDA + row] = v.y;
            As[(kq4 * 4 + 2) * LDA + row] = v.z;
            As[(kq4 * 4 + 3) * LDA + row] = v.w;
        }
        // B tile: 16 k x 128 cols
#pragma unroll
        for (int q = 0; q < 2; q++) {
            int slot = tid + q * 256;
            int nn = slot >> 2;
            int kq4 = slot & 3;
            int n = n0 + nn;
            int t = n >> 4, b = n & 15;
            float4 v = *(const float4*)&x[((size_t)b * Tt + t) * Ii + k0 + kq4 * 4];
            Bs[(kq4 * 4 + 0) * LDA + nn] = v.x;
            Bs[(kq4 * 4 + 1) * LDA + nn] = v.y;
            Bs[(kq4 * 4 + 2) * LDA + nn] = v.z;
            Bs[(kq4 * 4 + 3) * LDA + nn] = v.w;
        }
        __syncthreads();
#pragma unroll
        for (int kk = 0; kk < BK; kk++) {
            float a[8], bf[8];
            *(float4*)&a[0] = *(const float4*)&As[kk * LDA + ty * 8];
            *(float4*)&a[4] = *(const float4*)&As[kk * LDA + ty * 8 + 4];
            *(float4*)&bf[0] = *(const float4*)&Bs[kk * LDA + tx * 8];
            *(float4*)&bf[4] = *(const float4*)&Bs[kk * LDA + tx * 8 + 4];
#pragma unroll
            for (int i = 0; i < 8; i++)
#pragma unroll
                for (int j = 0; j < 8; j++)
                    acc[i][j] = fmaf(a[i], bf[j], acc[i][j]);
        }
        __syncthreads();
    }
    // epilogue: add fused bias, store as [t][r][b]
#pragma unroll
    for (int mm = 0; mm < 8; mm++) {
        int r = m0 + ty * 8 + mm;
        float bias = d_bsum[r];
#pragma unroll
        for (int nq = 0; nq < 2; nq++) {
            int n = n0 + tx * 8 + nq * 4;
            int t = n >> 4, b = n & 15;  // b in {0,4,8,12}; 4 cols share t
            float4 v;
            v.x = acc[mm][nq * 4 + 0] + bias;
            v.y = acc[mm][nq * 4 + 1] + bias;
            v.z = acc[mm][nq * 4 + 2] + bias;
            v.w = acc[mm][nq * 4 + 3] + bias;
            *(float4*)&d_XG[(size_t)t * (RR * Bb) + (size_t)r * Bb + b] = v;
        }
    }
}

// ---------------- phase 2: persistent recurrent kernel -----------------------
// 128 CTAs x 256 threads. CTA m owns permuted gate rows [16m,16m+16) ->
// hidden units [4m,4m+4), all 16 batches. Grid barrier per timestep.
#define WH_STRIDE 520   // 512 + 8: kills the 512 % 32 == 0 bank conflict

__device__ __forceinline__ float sigmoidf_(float x) {
    return 1.f / (1.f + __expf(-x));
}

__global__ __launch_bounds__(256, 1) void lstm_kernel(const float* __restrict__ c0,
                                                      float* __restrict__ out,
                                                      float* __restrict__ hT,
                                                      float* __restrict__ cT) {
    extern __shared__ float sm[];
    float*  Wh_s    = sm;                         // 16 * 520
    float*  h_s     = Wh_s + 16 * WH_STRIDE;      // 512 * 16   [k][b]
    float4* gred    = (float4*)(h_s + Hh * Bb);   // 256 float4 (k-split partials)
    float*  gates_s = (float*)(gred + 256);       // 16 * 16    [rl][b]
    float*  c_s     = gates_s + 256;              // 64         [jj][b]

    const int tid = threadIdx.x;
    const int m = blockIdx.x;
    const int kq = tid >> 6;       // k-split 0..3 (128 k each)
    const int s  = tid & 63;
    const int rl = s >> 2;         // local gate row 0..15
    const int bq = s & 3;          // batch quad 0..3

    // Wh slice -> SMEM (once)
    {
        const float4* src = (const float4*)(d_WhP + (size_t)m * 16 * Hh);
        for (int i = tid; i < 16 * Hh / 4; i += 256) {
            int rr = i >> 7;
            int k4 = i & 127;
            *(float4*)&Wh_s[rr * WH_STRIDE + k4 * 4] = src[i];
        }
    }
    const int jj = tid >> 4, bb = tid & 15;   // valid when tid < 64
    if (tid < 64) c_s[tid] = c0[bb * Hh + (m * 4 + jj)];
    __syncthreads();

    const unsigned nCTA = gridDim.x;
    float hlast = 0.f;

    for (int t = 0; t < Tt; t++) {
        const float4* cur = (const float4*)d_HBUF[t & 1];

        // xg for this step (only k-split 0 needs it; coalesced, streaming)
        float4 xgv = make_float4(0.f, 0.f, 0.f, 0.f);
        if (kq == 0)
            xgv = __ldcs((const float4*)(d_XG + (size_t)t * (RR * Bb)) +
                         ((m * 16 + rl) * 4 + bq));

        // cooperative copy h -> SMEM, bypassing (potentially stale) L1
        float4* h_s4 = (float4*)h_s;
#pragma unroll
        for (int i = tid; i < (Hh * Bb) / 4; i += 256)
            h_s4[i] = __ldcg(cur + i);
        __syncthreads();

        // partial gates: rows rl, batches 4bq..4bq+3, k in [128kq, 128kq+128)
        float4 acc = make_float4(0.f, 0.f, 0.f, 0.f);
        const float* wrow  = Wh_s + rl * WH_STRIDE + kq * 128;
        const float* hbase = h_s + kq * 128 * Bb + bq * 4;
#pragma unroll 8
        for (int k = 0; k < 128; k++) {
            float  w  = wrow[k];
            float4 hv = *(const float4*)(hbase + k * Bb);
            acc.x = fmaf(w, hv.x, acc.x);
            acc.y = fmaf(w, hv.y, acc.y);
            acc.z = fmaf(w, hv.z, acc.z);
            acc.w = fmaf(w, hv.w, acc.w);
        }
        gred[tid] = acc;
        __syncthreads();

        if (kq == 0) {
            float4 a0 = gred[s], a1 = gred[64 + s], a2 = gred[128 + s], a3 = gred[192 + s];
            float4 g;
            g.x = xgv.x + a0.x + a1.x + a2.x + a3.x;
            g.y = xgv.y + a0.y + a1.y + a2.y + a3.y;
            g.z = xgv.z + a0.z + a1.z + a2.z + a3.z;
            g.w = xgv.w + a0.w + a1.w + a2.w + a3.w;
            *(float4*)&gates_s[rl * 16 + bq * 4] = g;
        }
        __syncthreads();

        if (tid < 64) {
            float gi = gates_s[(jj * 4 + 0) * 16 + bb];
            float gf = gates_s[(jj * 4 + 1) * 16 + bb];
            float gg = gates_s[(jj * 4 + 2) * 16 + bb];
            float go = gates_s[(jj * 4 + 3) * 16 + bb];
            float ig = sigmoidf_(gi);
            float fg = sigmoidf_(gf);
            float gt = tanhf(gg);
            float og = sigmoidf_(go);
            float c = fmaf(fg, c_s[tid], ig * gt);
            float h = og * tanhf(c);
            c_s[tid] = c;
            int jglob = m * 4 + jj;
            d_HBUF[(t + 1) & 1][jglob * Bb + bb] = h;
            out[(size_t)bb * (Tt * Hh) + (size_t)t * Hh + jglob] = h;
            hlast = h;
            __threadfence();    // make h visible at device scope before arrival
        }
        __syncthreads();

        // grid-wide barrier (all 128 CTAs resident: grid <= #SMs)
        if (tid == 0) {
            unsigned target = nCTA * (unsigned)(t + 1);
            __threadfence();
            unsigned prev = atomicAdd(&d_bar_count, 1u);
            if (prev == target - 1u) {
                __threadfence();
                d_bar_flag = (unsigned)(t + 1);
            } else {
                while (d_bar_flag < (unsigned)(t + 1)) { }
            }
            __threadfence();
        }
        __syncthreads();
    }

    if (tid < 64) {
        int jglob = m * 4 + jj;
        hT[bb * Hh + jglob] = hlast;
        cT[bb * Hh + jglob] = c_s[tid];
    }
}

// ---------------- launch ------------------------------------------------------
extern "C" void kernel_launch(void* const* d_in, const int* in_sizes, int n_in,
                              void* d_out, int out_size) {
    const float* x  = (const float*)d_in[0];
    const float* h0 = (const float*)d_in[1];
    const float* c0 = (const float*)d_in[2];
    const float* Wi = (const float*)d_in[3];
    const float* bi = (const float*)d_in[4];
    const float* Wh = (const float*)d_in[5];
    const float* bh = (const float*)d_in[6];

    float* out = (float*)d_out;                       // [B,T,H]
    float* hT  = out + (size_t)Bb * Tt * Hh;          // [B,H]
    float* cT  = hT + (size_t)Bb * Hh;                // [B,H]

    const int lstm_smem = (16 * WH_STRIDE + Hh * Bb + 256 * 4 + 256 + 64) * 4;
    cudaFuncSetAttribute(lstm_kernel, cudaFuncAttributeMaxDynamicSharedMemorySize,
                         lstm_smem);

    permute_kernel<<<RR, 128>>>(Wi, Wh, bi, bh);
    init_kernel<<<32, 256>>>(h0);
    xgemm_kernel<<<dim3((Tt * Bb) / BN, RR / BM), 256>>>(x);
    lstm_kernel<<<128, 256, lstm_smem>>>(c0, out, hT, cT);
}

// round 3
// speedup vs baseline: 1.0167x; 1.0167x over previous
#include <cuda_runtime.h>
#include <math.h>

#define Bb 16
#define Tt 2048
#define Ii 512
#define Hh 512
#define RR 2048   // 4*H, permuted row order r = 4*j + g

// ---------------- persistent device scratch (no runtime allocation) ----------
__device__ float d_WiP[RR * Ii];                       // 4 MB  permuted Wi
__device__ float d_WhP[RR * Hh];                       // 4 MB  permuted Wh
__device__ float d_bsum[RR];                           // bi+bh, permuted
__device__ float d_XG[(size_t)Tt * RR * Bb];           // 268 MB, [t][r][b]
__device__ float d_HBUF[2][Hh * Bb];                   // double-buffered h, [k][b]
__device__ volatile unsigned d_flags[128 * 32];        // per-CTA step tags, 128B apart

// ---------------- f32x2 helpers (Blackwell packed fp32) ----------------------
__device__ __forceinline__ unsigned long long ffma2(unsigned long long a,
                                                    unsigned long long b,
                                                    unsigned long long c) {
    unsigned long long d;
    asm("fma.rn.f32x2 %0, %1, %2, %3;" : "=l"(d) : "l"(a), "l"(b), "l"(c));
    return d;
}
__device__ __forceinline__ unsigned long long packdup(float x) {
    unsigned long long r;
    asm("mov.b64 %0, {%1, %1};" : "=l"(r) : "f"(x));
    return r;
}
__device__ __forceinline__ float2 unpk(unsigned long long v) {
    float2 r;
    asm("mov.b64 {%0, %1}, %2;" : "=f"(r.x), "=f"(r.y) : "l"(v));
    return r;
}

__device__ __forceinline__ float sigmoidf_(float x) {
    return 1.f / (1.f + __expf(-x));
}
__device__ __forceinline__ float tanhf_(float x) {
    // (e^{2x}-1)/(e^{2x}+1) with hw ex2: rel err ~1e-6, ~6 instr
    float e = __expf(2.f * x);
    return (e - 1.f) / (e + 1.f);
}

// ---------------- phase 0a: permute weights, fuse biases ---------------------
__global__ void permute_kernel(const float* __restrict__ Wi,
                               const float* __restrict__ Wh,
                               const float* __restrict__ bi,
                               const float* __restrict__ bh) {
    int rnew = blockIdx.x;            // 0..2047
    int j = rnew >> 2, g = rnew & 3;
    int rold = g * Hh + j;
    const float4* wi4 = (const float4*)(Wi + (size_t)rold * Ii);
    const float4* wh4 = (const float4*)(Wh + (size_t)rold * Hh);
    float4* wiP4 = (float4*)(d_WiP + (size_t)rnew * Ii);
    float4* whP4 = (float4*)(d_WhP + (size_t)rnew * Hh);
    for (int k = threadIdx.x; k < Ii / 4; k += blockDim.x) wiP4[k] = wi4[k];
    for (int k = threadIdx.x; k < Hh / 4; k += blockDim.x) whP4[k] = wh4[k];
    if (threadIdx.x == 0) d_bsum[rnew] = bi[rold] + bh[rold];
}

// ---------------- phase 0b: init h buffer + flags ----------------------------
__global__ void init_kernel(const float* __restrict__ h0) {
    int idx = blockIdx.x * blockDim.x + threadIdx.x;   // 0..8191
    if (idx < Hh * Bb) {
        int j = idx >> 4, b = idx & 15;
        d_HBUF[0][idx] = h0[b * Hh + j];               // h_s layout [k][b]
    }
    if (idx < 128 * 32) d_flags[idx] = 0u;
}

// ---------------- phase 1: xg[t][r][b] = WiP @ x^T + bsum --------------------
// GEMM: M=2048 (r), N=32768 (n=(t,b)), K=512.  X[i][n] = x[b][t][i] (contig in i).
#define BM 128
#define BN 128
#define BK 16
#define LDA 132

__global__ __launch_bounds__(256, 2) void xgemm_kernel(const float* __restrict__ x) {
    __shared__ float As[BK * LDA];
    __shared__ float Bs[BK * LDA];
    const int tid = threadIdx.x;
    const int m0 = blockIdx.y * BM;
    const int n0 = blockIdx.x * BN;
    const int tx = tid & 15, ty = tid >> 4;

    unsigned long long acc[8][4];   // 8 rows x 4 column-pairs (f32x2)
#pragma unroll
    for (int i = 0; i < 8; i++)
#pragma unroll
        for (int j = 0; j < 4; j++) acc[i][j] = 0ull;

    for (int k0 = 0; k0 < Ii; k0 += BK) {
        // A tile: 128 rows x 16 k  (512 float4 slots)
#pragma unroll
        for (int q = 0; q < 2; q++) {
            int slot = tid + q * 256;
            int row = slot >> 2;
            int kq4 = slot & 3;
            float4 v = *(const float4*)&d_WiP[(size_t)(m0 + row) * Ii + k0 + kq4 * 4];
            As[(kq4 * 4 + 0) * LDA + row] = v.x;
            As[(kq4 * 4 + 1) * LDA + row] = v.y;
            As[(kq4 * 4 + 2) * LDA + row] = v.z;
            As[(kq4 * 4 + 3) * LDA + row] = v.w;
        }
        // B tile: 16 k x 128 cols
#pragma unroll
        for (int q = 0; q < 2; q++) {
            int slot = tid + q * 256;
            int nn = slot >> 2;
            int kq4 = slot & 3;
            int n = n0 + nn;
            int t = n >> 4, b = n & 15;
            float4 v = *(const float4*)&x[((size_t)b * Tt + t) * Ii + k0 + kq4 * 4];
            Bs[(kq4 * 4 + 0) * LDA + nn] = v.x;
            Bs[(kq4 * 4 + 1) * LDA + nn] = v.y;
            Bs[(kq4 * 4 + 2) * LDA + nn] = v.z;
            Bs[(kq4 * 4 + 3) * LDA + nn] = v.w;
        }
        __syncthreads();
#pragma unroll
        for (int kk = 0; kk < BK; kk++) {
            float a[8];
            *(float4*)&a[0] = *(const float4*)&As[kk * LDA + ty * 8];
            *(float4*)&a[4] = *(const float4*)&As[kk * LDA + ty * 8 + 4];
            ulonglong2 b01 = *(const ulonglong2*)&Bs[kk * LDA + tx * 8];
            ulonglong2 b23 = *(const ulonglong2*)&Bs[kk * LDA + tx * 8 + 4];
#pragma unroll
            for (int i = 0; i < 8; i++) {
                unsigned long long as = packdup(a[i]);
                acc[i][0] = ffma2(as, b01.x, acc[i][0]);
                acc[i][1] = ffma2(as, b01.y, acc[i][1]);
                acc[i][2] = ffma2(as, b23.x, acc[i][2]);
                acc[i][3] = ffma2(as, b23.y, acc[i][3]);
            }
        }
        __syncthreads();
    }
    // epilogue: add fused bias, store as [t][r][b]
#pragma unroll
    for (int mm = 0; mm < 8; mm++) {
        int r = m0 + ty * 8 + mm;
        float bias = d_bsum[r];
#pragma unroll
        for (int nq = 0; nq < 2; nq++) {
            int n = n0 + tx * 8 + nq * 4;
            int t = n >> 4, b = n & 15;  // b in {0,4,8,12}; 4 cols share t
            float2 u0 = unpk(acc[mm][nq * 2 + 0]);
            float2 u1 = unpk(acc[mm][nq * 2 + 1]);
            float4 v;
            v.x = u0.x + bias;
            v.y = u0.y + bias;
            v.z = u1.x + bias;
            v.w = u1.y + bias;
            *(float4*)&d_XG[(size_t)t * (RR * Bb) + (size_t)r * Bb + b] = v;
        }
    }
}

// ---------------- phase 2: persistent recurrent kernel -----------------------
// 128 CTAs x 256 threads. CTA m owns permuted gate rows [16m,16m+16) ->
// hidden units [4m,4m+4), all 16 batches. Distributed-flag barrier per step.
#define WH2_STRIDE 513   // float2 units; lane rl -> distinct bank pairs

__global__ __launch_bounds__(256, 1) void lstm_kernel(const float* __restrict__ c0,
                                                      float* __restrict__ out,
                                                      float* __restrict__ hT,
                                                      float* __restrict__ cT) {
    extern __shared__ float sm[];
    float*  Wh2_s   = sm;                            // 16 * 513 float2 = 16416 floats
    float*  h_s     = Wh2_s + 16 * WH2_STRIDE * 2;   // 512 * 16   [k][b]
    float4* gred    = (float4*)(h_s + Hh * Bb);      // 256 float4 (k-split partials)
    float*  gates_s = (float*)(gred + 256);          // 16 * 16    [rl][b]
    float*  c_s     = gates_s + 256;                 // 64         [jj][b]

    const int tid = threadIdx.x;
    const int m = blockIdx.x;
    const int kq = tid >> 6;       // k-split 0..3 (128 k each)
    const int s  = tid & 63;
    const int rl = s >> 2;         // local gate row 0..15
    const int bq = s & 3;          // batch quad 0..3

    // Wh slice -> SMEM, duplicated as (w,w) pairs for FFMA2 (once)
    {
        float2* w2 = (float2*)Wh2_s;
        const float* src = d_WhP + (size_t)m * 16 * Hh;
        for (int i = tid; i < 16 * Hh; i += 256) {
            int rr = i >> 9;
            int k  = i & 511;
            float w = src[i];
            w2[rr * WH2_STRIDE + k] = make_float2(w, w);
        }
    }
    const int jj = tid >> 4, bb = tid & 15;   // valid when tid < 64
    if (tid < 64) c_s[tid] = c0[bb * Hh + (m * 4 + jj)];
    __syncthreads();

    float hlast = 0.f;

    const unsigned long long* w2p =
        (const unsigned long long*)Wh2_s + rl * WH2_STRIDE + kq * 128;
    const ulonglong2* hp =
        (const ulonglong2*)(h_s) + (size_t)kq * 128 * 4 + bq;  // [k][bq], stride 4/k

    for (int t = 0; t < Tt; t++) {
        const float4* cur = (const float4*)d_HBUF[t & 1];

        // xg for this step (only k-split 0 needs it; coalesced, streaming)
        float4 xgv = make_float4(0.f, 0.f, 0.f, 0.f);
        if (kq == 0)
            xgv = __ldcs((const float4*)(d_XG + (size_t)t * (RR * Bb)) +
                         ((m * 16 + rl) * 4 + bq));

        // wait until every CTA has produced h for step t (flag >= t)
        if (tid < 128) {
            while (d_flags[tid * 32] < (unsigned)t) { }
            __threadfence();
        }
        __syncthreads();

        // cooperative copy h -> SMEM, bypassing (potentially stale) L1
        float4* h_s4 = (float4*)h_s;
#pragma unroll
        for (int i = tid; i < (Hh * Bb) / 4; i += 256)
            h_s4[i] = __ldcg(cur + i);
        __syncthreads();

        // partial gates: row rl, batches 4bq..4bq+3, k in [128kq, 128kq+128)
        unsigned long long acc0 = 0ull, acc1 = 0ull;
#pragma unroll 16
        for (int k = 0; k < 128; k++) {
            unsigned long long w2 = w2p[k];
            ulonglong2 hv = hp[(size_t)k * 4];
            acc0 = ffma2(w2, hv.x, acc0);
            acc1 = ffma2(w2, hv.y, acc1);
        }
        {
            float2 p0 = unpk(acc0), p1 = unpk(acc1);
            gred[tid] = make_float4(p0.x, p0.y, p1.x, p1.y);
        }
        __syncthreads();

        if (kq == 0) {
            float4 a0 = gred[s], a1 = gred[64 + s], a2 = gred[128 + s], a3 = gred[192 + s];
            float4 g;
            g.x = xgv.x + a0.x + a1.x + a2.x + a3.x;
            g.y = xgv.y + a0.y + a1.y + a2.y + a3.y;
            g.z = xgv.z + a0.z + a1.z + a2.z + a3.z;
            g.w = xgv.w + a0.w + a1.w + a2.w + a3.w;
            *(float4*)&gates_s[rl * 16 + bq * 4] = g;
        }
        __syncthreads();

        if (tid < 64) {
            float gi = gates_s[(jj * 4 + 0) * 16 + bb];
            float gf = gates_s[(jj * 4 + 1) * 16 + bb];
            float gg = gates_s[(jj * 4 + 2) * 16 + bb];
            float go = gates_s[(jj * 4 + 3) * 16 + bb];
            float ig = sigmoidf_(gi);
            float fg = sigmoidf_(gf);
            float gt = tanhf_(gg);
            float og = sigmoidf_(go);
            float c = fmaf(fg, c_s[tid], ig * gt);
            float h = og * tanhf_(c);
            c_s[tid] = c;
            int jglob = m * 4 + jj;
            d_HBUF[(t + 1) & 1][jglob * Bb + bb] = h;
            out[(size_t)bb * (Tt * Hh) + (size_t)t * Hh + jglob] = h;
            hlast = h;
        }
        __syncthreads();                    // h writes done CTA-wide

        if (tid == 0) {
            __threadfence();                // publish h before tag (cumulative)
            d_flags[m * 32] = (unsigned)(t + 1);
        }
    }

    if (tid < 64) {
        int jglob = m * 4 + jj;
        hT[bb * Hh + jglob] = hlast;
        cT[bb * Hh + jglob] = c_s[tid];
    }
}

// ---------------- launch ------------------------------------------------------
extern "C" void kernel_launch(void* const* d_in, const int* in_sizes, int n_in,
                              void* d_out, int out_size) {
    const float* x  = (const float*)d_in[0];
    const float* h0 = (const float*)d_in[1];
    const float* c0 = (const float*)d_in[2];
    const float* Wi = (const float*)d_in[3];
    const float* bi = (const float*)d_in[4];
    const float* Wh = (const float*)d_in[5];
    const float* bh = (const float*)d_in[6];

    float* out = (float*)d_out;                       // [B,T,H]
    float* hT  = out + (size_t)Bb * Tt * Hh;          // [B,H]
    float* cT  = hT + (size_t)Bb * Hh;                // [B,H]

    const int lstm_smem =
        (16 * WH2_STRIDE * 2 + Hh * Bb + 256 * 4 + 256 + 64) * 4;
    cudaFuncSetAttribute(lstm_kernel, cudaFuncAttributeMaxDynamicSharedMemorySize,
                         lstm_smem);

    permute_kernel<<<RR, 128>>>(Wi, Wh, bi, bh);
    init_kernel<<<32, 256>>>(h0);
    xgemm_kernel<<<dim3((Tt * Bb) / BN, RR / BM), 256>>>(x);
    lstm_kernel<<<128, 256, lstm_smem>>>(c0, out, hT, cT);
}